// round 6
// baseline (speedup 1.0000x reference)
#include <cuda_runtime.h>
#include <cstdint>

#define N_NODES 100000
#define N_EDGES 1600000
#define IN_CH   128
#define HIDDEN  64
#define NCLS    40

#define NB_GEMM1 1563                 // ceil(100000/64) 64-row tiles
#define NB_DEGB  1563                 // deg blocks (128 thr x 8 edges)
#define DEG_T    (NB_DEGB * 128)      // 200064 threads; x8 covers 1.6M
#define NB_FILL  1563                 // fill blocks (256 thr x 4 edges)
#define FILL_T   (NB_FILL * 256)

// ---------------- scratch (device globals; no allocation allowed) ----------
__device__ int   g_is64;
__device__ int   g_deg[N_NODES];
__device__ int   g_off[N_NODES + 1];
__device__ int   g_cur[N_NODES];
__device__ float g_dinv[N_NODES];
__device__ int   g_bsum[128];
__device__ int2  g_adj[N_EDGES];                     // (src, norm-as-bits), grouped by dst
__device__ float g_hw  [(size_t)N_NODES * HIDDEN];   // X @ W1
__device__ float g_agg1[(size_t)N_NODES * HIDDEN];   // layer1 aggregated (pre-relu)
__device__ float g_h2w [(size_t)N_NODES * NCLS];     // relu(agg1) @ W2

// ---------------- packed f32x2 helpers --------------------------------------
__device__ __forceinline__ unsigned long long ffma2(unsigned long long a,
                                                    unsigned long long b,
                                                    unsigned long long c) {
    unsigned long long d;
    asm("fma.rn.f32x2 %0, %1, %2, %3;" : "=l"(d) : "l"(a), "l"(b), "l"(c));
    return d;
}
__device__ __forceinline__ unsigned long long pack2(float a) {
    unsigned long long d;
    asm("mov.b64 %0, {%1, %1};" : "=l"(d) : "f"(a));
    return d;
}

// ---------------- prep: zero degrees + detect index dtype -------------------
// int64 indices (<2^31) have zero high words at every odd int32 position.
__global__ void prep_kernel(const int* __restrict__ w) {
    int i = blockIdx.x * blockDim.x + threadIdx.x;
    if (i < N_NODES) g_deg[i] = 0;
    if (blockIdx.x == 0) {
        __shared__ int acc;
        if (threadIdx.x == 0) acc = 0;
        __syncthreads();
        int v = 0;
        for (int j = threadIdx.x; j < 4096; j += blockDim.x) v |= w[2 * j + 1];
        atomicOr(&acc, v);
        __syncthreads();
        if (threadIdx.x == 0) g_is64 = (acc == 0) ? 1 : 0;
    }
}

// ---------------- merged: deg histogram blocks + gemm1 tile blocks ----------
// deg blocks first (critical path), gemm1 tiles after. 128 threads each.
__global__ void degmm_kernel(const float* __restrict__ x,
                             const float* __restrict__ W1,
                             float* __restrict__ C,
                             const int* __restrict__ w) {
    extern __shared__ float smem[];
    int bid = blockIdx.x;
    int tid = threadIdx.x;

    if (bid < NB_DEGB) {               // ---- degree histogram ----
        int idx = bid * 128 + tid;
        int is64 = g_is64;
#pragma unroll
        for (int j = 0; j < 8; j++) {
            int e = idx + j * DEG_T;
            if (e < N_EDGES) {
                int d = is64 ? w[2 * (N_EDGES + e)] : w[N_EDGES + e];
                if ((unsigned)d >= N_NODES) d = 0;
                atomicAdd(&g_deg[d], 1);
            }
        }
        return;
    }

    // ---- gemm1 tile: 64 rows x 64 cols, K=128, 128 threads ----
    constexpr int KDIM = IN_CH, NDIM = HIDDEN, ROWS = 64, NT = 128;
    constexpr int PITCH = KDIM + 4;
    float* sA = smem;                  // [64][132]
    float* sW = smem + ROWS * PITCH;   // [128][64]
    const int rowbase = (bid - NB_DEGB) * ROWS;

    for (int v = tid; v < KDIM * NDIM / 4; v += NT)
        ((float4*)sW)[v] = ((const float4*)W1)[v];

    constexpr int KC4 = KDIM / 4;
    for (int v = tid; v < ROWS * KC4; v += NT) {
        int r  = v / KC4;
        int kc = (v - r * KC4) * 4;
        int row = rowbase + r;
        float4 a = make_float4(0.f, 0.f, 0.f, 0.f);
        if (row < N_NODES) a = *(const float4*)(x + (size_t)row * KDIM + kc);
        *(float4*)(sA + r * PITCH + kc) = a;
    }
    __syncthreads();

    const int ty = tid / 8, tx = tid & 7;  // 16 x 8
    unsigned long long acc[4][4];
#pragma unroll
    for (int i = 0; i < 4; i++)
#pragma unroll
        for (int j = 0; j < 4; j++) acc[i][j] = 0ull;

#pragma unroll 4
    for (int k = 0; k < KDIM; k++) {
        ulonglong2 b01 = *(const ulonglong2*)(sW + k * NDIM + 8 * tx);
        ulonglong2 b23 = *(const ulonglong2*)(sW + k * NDIM + 8 * tx + 4);
#pragma unroll
        for (int i = 0; i < 4; i++) {
            unsigned long long pa = pack2(sA[(4 * ty + i) * PITCH + k]);
            acc[i][0] = ffma2(pa, b01.x, acc[i][0]);
            acc[i][1] = ffma2(pa, b01.y, acc[i][1]);
            acc[i][2] = ffma2(pa, b23.x, acc[i][2]);
            acc[i][3] = ffma2(pa, b23.y, acc[i][3]);
        }
    }

#pragma unroll
    for (int i = 0; i < 4; i++) {
        int row = rowbase + 4 * ty + i;
        if (row < N_NODES) {
            ulonglong2* p = (ulonglong2*)(C + (size_t)row * NDIM + 8 * tx);
            p[0] = make_ulonglong2(acc[i][0], acc[i][1]);
            p[1] = make_ulonglong2(acc[i][2], acc[i][3]);
        }
    }
}

// ---------------- scan: A = per-block sums; C = full scan (B fused) ---------
#define SCAN_NB  128
#define SCAN_TPB 256
#define SCAN_PER 4        // 128*256*4 = 131072 >= N_NODES

__global__ void scanA_kernel() {
    __shared__ int red[SCAN_TPB];
    int t = threadIdx.x;
    int base = (blockIdx.x * SCAN_TPB + t) * SCAN_PER;
    int s = 0;
#pragma unroll
    for (int j = 0; j < SCAN_PER; j++) {
        int i = base + j;
        if (i < N_NODES) s += g_deg[i];
    }
    red[t] = s;
    __syncthreads();
    for (int o = SCAN_TPB / 2; o > 0; o >>= 1) {
        if (t < o) red[t] += red[t + o];
        __syncthreads();
    }
    if (t == 0) g_bsum[blockIdx.x] = red[0];
}

// scanC: every block redundantly scans the 128 block sums (cheap), then does
// its own per-element exclusive scan; writes g_off, g_cur, g_dinv.
__global__ void scanC_kernel() {
    __shared__ int top[SCAN_NB];
    __shared__ int p[SCAN_TPB];
    int t = threadIdx.x;

    if (t < SCAN_NB) top[t] = g_bsum[t];
    __syncthreads();
    for (int o = 1; o < SCAN_NB; o <<= 1) {
        int v = (t >= o && t < SCAN_NB) ? top[t - o] : 0;
        __syncthreads();
        if (t < SCAN_NB) top[t] += v;
        __syncthreads();
    }
    int bpre = (blockIdx.x > 0) ? top[blockIdx.x - 1] : 0;
    if (blockIdx.x == SCAN_NB - 1 && t == 0) g_off[N_NODES] = top[SCAN_NB - 1];

    int base = (blockIdx.x * SCAN_TPB + t) * SCAN_PER;
    int loc[SCAN_PER];
    int s = 0;
#pragma unroll
    for (int j = 0; j < SCAN_PER; j++) {
        int i = base + j;
        int d = (i < N_NODES) ? g_deg[i] : 0;
        loc[j] = s;
        s += d;
    }
    p[t] = s;
    __syncthreads();
    for (int o = 1; o < SCAN_TPB; o <<= 1) {
        int v = (t >= o) ? p[t - o] : 0;
        __syncthreads();
        p[t] += v;
        __syncthreads();
    }
    int pre = bpre + ((t > 0) ? p[t - 1] : 0);
#pragma unroll
    for (int j = 0; j < SCAN_PER; j++) {
        int i = base + j;
        if (i < N_NODES) {
            int o = pre + loc[j];
            g_off[i] = o;
            g_cur[i] = o;
            g_dinv[i] = rsqrtf((float)(g_deg[i] + 1));  // +1 self loop
        }
    }
}

// counting-sort edges by dst into g_adj (re-decodes ei; norm precomputed)
__global__ void fill_kernel(const int* __restrict__ w) {
    int idx = blockIdx.x * 256 + threadIdx.x;
    int is64 = g_is64;
#pragma unroll
    for (int j = 0; j < 4; j++) {
        int e = idx + j * FILL_T;
        if (e < N_EDGES) {
            int s, d;
            if (is64) { s = w[2 * e]; d = w[2 * (N_EDGES + e)]; }
            else      { s = w[e];     d = w[N_EDGES + e]; }
            if ((unsigned)s >= N_NODES) s = 0;
            if ((unsigned)d >= N_NODES) d = 0;
            int pos = atomicAdd(&g_cur[d], 1);
            g_adj[pos] = make_int2(s, __float_as_int(g_dinv[s] * g_dinv[d]));
        }
    }
}

// ---------------- GEMM2: C[M,40] = relu(A[M,64]) * W[64,40] ----------------
template<int KDIM, int NDIM, int ROWS>
__global__ void gemm2_kernel(const float* __restrict__ A,
                             const float* __restrict__ W,
                             float* __restrict__ C, int M) {
    constexpr int TX    = NDIM / 8;     // 5
    constexpr int TY    = ROWS / 4;     // 32
    constexpr int NT    = TX * TY;      // 160
    constexpr int PITCH = KDIM + 4;
    extern __shared__ float smem[];
    float* sA = smem;
    float* sW = smem + ROWS * PITCH;

    const int tid     = threadIdx.x;
    const int rowbase = blockIdx.x * ROWS;

    for (int v = tid; v < KDIM * NDIM / 4; v += NT)
        ((float4*)sW)[v] = ((const float4*)W)[v];

    constexpr int KC4 = KDIM / 4;
    for (int v = tid; v < ROWS * KC4; v += NT) {
        int r  = v / KC4;
        int kc = (v - r * KC4) * 4;
        int row = rowbase + r;
        float4 a = make_float4(0.f, 0.f, 0.f, 0.f);
        if (row < M) a = *(const float4*)(A + (size_t)row * KDIM + kc);
        a.x = fmaxf(a.x, 0.f); a.y = fmaxf(a.y, 0.f);
        a.z = fmaxf(a.z, 0.f); a.w = fmaxf(a.w, 0.f);
        *(float4*)(sA + r * PITCH + kc) = a;
    }
    __syncthreads();

    const int ty = tid / TX, tx = tid - (tid / TX) * TX;
    unsigned long long acc[4][4];
#pragma unroll
    for (int i = 0; i < 4; i++)
#pragma unroll
        for (int j = 0; j < 4; j++) acc[i][j] = 0ull;

#pragma unroll 4
    for (int k = 0; k < KDIM; k++) {
        ulonglong2 b01 = *(const ulonglong2*)(sW + k * NDIM + 8 * tx);
        ulonglong2 b23 = *(const ulonglong2*)(sW + k * NDIM + 8 * tx + 4);
#pragma unroll
        for (int i = 0; i < 4; i++) {
            unsigned long long pa = pack2(sA[(4 * ty + i) * PITCH + k]);
            acc[i][0] = ffma2(pa, b01.x, acc[i][0]);
            acc[i][1] = ffma2(pa, b01.y, acc[i][1]);
            acc[i][2] = ffma2(pa, b23.x, acc[i][2]);
            acc[i][3] = ffma2(pa, b23.y, acc[i][3]);
        }
    }

#pragma unroll
    for (int i = 0; i < 4; i++) {
        int row = rowbase + 4 * ty + i;
        if (row < M) {
            ulonglong2* p = (ulonglong2*)(C + (size_t)row * NDIM + 8 * tx);
            p[0] = make_ulonglong2(acc[i][0], acc[i][1]);
            p[1] = make_ulonglong2(acc[i][2], acc[i][3]);
        }
    }
}

// ---------------- CSR aggregation with adj prefetch -------------------------
// out[i] = bias + dinv_i^2*feat[i] + sum_j norm_ij*feat[src_j]
// one warp per node; lane groups of V4 lanes own float4 chunks; EP edges/iter.
template<int CH>
__global__ void aggregate_kernel(const float* __restrict__ feat,
                                 const float* __restrict__ bias,
                                 float* __restrict__ out) {
    constexpr int V4 = CH / 4;       // 16 (CH=64) or 10 (CH=40)
    constexpr int EP = 32 / V4;      // 2 or 3
    int node = (blockIdx.x * blockDim.x + threadIdx.x) >> 5;
    if (node >= N_NODES) return;
    int lane = threadIdx.x & 31;
    int eg = lane / V4;              // edge group
    int c  = lane - eg * V4;         // float4 index within row
    bool act = eg < EP;

    const int beg = g_off[node];
    const int end = g_off[node + 1];

    float4 acc = make_float4(0.f, 0.f, 0.f, 0.f);
    if (eg == 0) {                   // self-loop + bias in group 0 only
        float dv = g_dinv[node];
        float s  = dv * dv;
        float4 f  = ((const float4*)(feat + (size_t)node * CH))[c];
        float4 bb = ((const float4*)bias)[c];
        acc.x = fmaf(s, f.x, bb.x);
        acc.y = fmaf(s, f.y, bb.y);
        acc.z = fmaf(s, f.z, bb.z);
        acc.w = fmaf(s, f.w, bb.w);
    }

    // software-pipelined edge loop; dummy entries carry norm=0 (src=0 safe)
    int2 p = make_int2(0, 0);
    if (act && beg + eg < end) p = g_adj[beg + eg];
    for (int k = beg; k < end; k += EP) {
        int kn = k + EP;
        int2 pn = make_int2(0, 0);
        if (act && kn + eg < end) pn = g_adj[kn + eg];
        float nrm = __int_as_float(p.y);
        float4 v = ((const float4*)(feat + (size_t)p.x * CH))[c];
        acc.x = fmaf(nrm, v.x, acc.x);
        acc.y = fmaf(nrm, v.y, acc.y);
        acc.z = fmaf(nrm, v.z, acc.z);
        acc.w = fmaf(nrm, v.w, acc.w);
        p = pn;
    }

    // reduce groups 1..EP-1 into group 0 (shfls read pre-update values)
    const unsigned m = 0xffffffffu;
    float x1 = __shfl_down_sync(m, acc.x, V4);
    float y1 = __shfl_down_sync(m, acc.y, V4);
    float z1 = __shfl_down_sync(m, acc.z, V4);
    float w1 = __shfl_down_sync(m, acc.w, V4);
    if (EP > 2) {
        float x2 = __shfl_down_sync(m, acc.x, 2 * V4);
        float y2 = __shfl_down_sync(m, acc.y, 2 * V4);
        float z2 = __shfl_down_sync(m, acc.z, 2 * V4);
        float w2 = __shfl_down_sync(m, acc.w, 2 * V4);
        x1 += x2; y1 += y2; z1 += z2; w1 += w2;
    }
    acc.x += x1; acc.y += y1; acc.z += z1; acc.w += w1;

    if (eg == 0)
        ((float4*)(out + (size_t)node * CH))[c] = acc;
}

// ---------------- launch ----------------------------------------------------
extern "C" void kernel_launch(void* const* d_in, const int* in_sizes, int n_in,
                              void* d_out, int out_size) {
    const float* x  = (const float*)d_in[0];
    const int*   ei = (const int*)d_in[1];      // int32 words of edge_index (either dtype)
    const float* W1 = (const float*)d_in[2];
    const float* b1 = (const float*)d_in[3];
    const float* W2 = (const float*)d_in[4];
    const float* b2 = (const float*)d_in[5];
    float*       out = (float*)d_out;

    void *hw_p, *agg1_p, *h2w_p;
    cudaGetSymbolAddress(&hw_p,   g_hw);
    cudaGetSymbolAddress(&agg1_p, g_agg1);
    cudaGetSymbolAddress(&h2w_p,  g_h2w);

    constexpr int TPB = 256;
    const int nb_nodes = (N_NODES + TPB - 1) / TPB;

    // 1) zero degrees + detect dtype
    prep_kernel<<<nb_nodes, TPB>>>(ei);

    // 2) merged: deg histogram + gemm1 (independent of each other)
    constexpr int SMEM1 = (64 * (IN_CH + 4) + IN_CH * HIDDEN) * sizeof(float); // 66560
    cudaFuncSetAttribute(degmm_kernel, cudaFuncAttributeMaxDynamicSharedMemorySize, SMEM1);
    degmm_kernel<<<NB_DEGB + NB_GEMM1, 128, SMEM1>>>(x, W1, (float*)hw_p, ei);

    // 3-4) scan (B fused into C)
    scanA_kernel<<<SCAN_NB, SCAN_TPB>>>();
    scanC_kernel<<<SCAN_NB, SCAN_TPB>>>();

    // 5) counting sort into dst-grouped adjacency
    fill_kernel<<<NB_FILL, 256>>>(ei);

    // 6) layer1 aggregation (+bias,+self)
    const int nb_warps = (N_NODES * 32 + TPB - 1) / TPB;  // 1 warp per node
    aggregate_kernel<HIDDEN><<<nb_warps, TPB>>>((const float*)hw_p, b1, (float*)agg1_p);

    // 7) gemm2 (relu fused into A-load)
    constexpr int SMEM2 = (128 * (HIDDEN + 4) + HIDDEN * NCLS) * sizeof(float); // 45056
    cudaFuncSetAttribute(gemm2_kernel<HIDDEN, NCLS, 128>,
                         cudaFuncAttributeMaxDynamicSharedMemorySize, SMEM2);
    gemm2_kernel<HIDDEN, NCLS, 128>
        <<<(N_NODES + 127) / 128, (NCLS / 8) * 32, SMEM2>>>((const float*)agg1_p, W2,
                                                            (float*)h2w_p, N_NODES);

    // 8) layer2 aggregation -> output
    aggregate_kernel<NCLS><<<nb_warps, TPB>>>((const float*)h2w_p, b2, out);
}

// round 7
// speedup vs baseline: 1.4835x; 1.4835x over previous
#include <cuda_runtime.h>
#include <cstdint>

#define N_NODES 100000
#define N_EDGES 1600000
#define IN_CH   128
#define HIDDEN  64
#define NCLS    40

// ---------------- scratch (device globals; no allocation allowed) ----------
__device__ int   g_is64;
__device__ int   g_deg[N_NODES];
__device__ int   g_off[N_NODES + 1];
__device__ int   g_cur[N_NODES];
__device__ float g_dinv[N_NODES];
__device__ int   g_bsum[128];
__device__ int2  g_adj[N_EDGES];                     // (src, norm-as-bits), grouped by dst
__device__ float g_hw  [(size_t)N_NODES * HIDDEN];   // X @ W1
__device__ float g_agg1[(size_t)N_NODES * HIDDEN];   // layer1 aggregated (pre-relu)
__device__ float g_h2w [(size_t)N_NODES * NCLS];     // relu(agg1) @ W2

// ---------------- packed f32x2 helpers --------------------------------------
__device__ __forceinline__ unsigned long long ffma2(unsigned long long a,
                                                    unsigned long long b,
                                                    unsigned long long c) {
    unsigned long long d;
    asm("fma.rn.f32x2 %0, %1, %2, %3;" : "=l"(d) : "l"(a), "l"(b), "l"(c));
    return d;
}
__device__ __forceinline__ unsigned long long pack2(float a) {
    unsigned long long d;
    asm("mov.b64 %0, {%1, %1};" : "=l"(d) : "f"(a));
    return d;
}

// ---------------- prep: zero degrees + detect index dtype -------------------
// int64 indices (<2^31) have zero high words at every odd int32 position.
__global__ void prep_kernel(const int* __restrict__ w) {
    int i = blockIdx.x * blockDim.x + threadIdx.x;
    if (i < N_NODES) g_deg[i] = 0;
    if (blockIdx.x == 0) {
        __shared__ int acc;
        if (threadIdx.x == 0) acc = 0;
        __syncthreads();
        int v = 0;
        for (int j = threadIdx.x; j < 4096; j += blockDim.x) v |= w[2 * j + 1];
        atomicOr(&acc, v);
        __syncthreads();
        if (threadIdx.x == 0) g_is64 = (acc == 0) ? 1 : 0;
    }
}

#define NB_EDGE4 1563                    // ceil(1.6M / (256*4))
#define EDGE4_T  (NB_EDGE4 * 256)

__global__ void deg_kernel(const int* __restrict__ w) {
    int idx = blockIdx.x * 256 + threadIdx.x;
    int is64 = g_is64;
#pragma unroll
    for (int j = 0; j < 4; j++) {
        int e = idx + j * EDGE4_T;
        if (e < N_EDGES) {
            int d = is64 ? w[2 * (N_EDGES + e)] : w[N_EDGES + e];
            if ((unsigned)d >= N_NODES) d = 0;
            atomicAdd(&g_deg[d], 1);
        }
    }
}

// ---------------- scan: A = per-block sums; C = full scan (B fused) ---------
#define SCAN_NB  128
#define SCAN_TPB 256
#define SCAN_PER 4        // 128*256*4 = 131072 >= N_NODES

__global__ void scanA_kernel() {
    __shared__ int red[SCAN_TPB];
    int t = threadIdx.x;
    int base = (blockIdx.x * SCAN_TPB + t) * SCAN_PER;
    int s = 0;
#pragma unroll
    for (int j = 0; j < SCAN_PER; j++) {
        int i = base + j;
        if (i < N_NODES) s += g_deg[i];
    }
    red[t] = s;
    __syncthreads();
    for (int o = SCAN_TPB / 2; o > 0; o >>= 1) {
        if (t < o) red[t] += red[t + o];
        __syncthreads();
    }
    if (t == 0) g_bsum[blockIdx.x] = red[0];
}

// scanC: every block redundantly scans the 128 block sums (cheap), then its
// own per-element exclusive scan; writes g_off, g_cur, g_dinv.
__global__ void scanC_kernel() {
    __shared__ int top[SCAN_NB];
    __shared__ int p[SCAN_TPB];
    int t = threadIdx.x;

    if (t < SCAN_NB) top[t] = g_bsum[t];
    __syncthreads();
    for (int o = 1; o < SCAN_NB; o <<= 1) {
        int v = (t >= o && t < SCAN_NB) ? top[t - o] : 0;
        __syncthreads();
        if (t < SCAN_NB) top[t] += v;
        __syncthreads();
    }
    int bpre = (blockIdx.x > 0) ? top[blockIdx.x - 1] : 0;
    if (blockIdx.x == SCAN_NB - 1 && t == 0) g_off[N_NODES] = top[SCAN_NB - 1];

    int base = (blockIdx.x * SCAN_TPB + t) * SCAN_PER;
    int loc[SCAN_PER];
    int s = 0;
#pragma unroll
    for (int j = 0; j < SCAN_PER; j++) {
        int i = base + j;
        int d = (i < N_NODES) ? g_deg[i] : 0;
        loc[j] = s;
        s += d;
    }
    p[t] = s;
    __syncthreads();
    for (int o = 1; o < SCAN_TPB; o <<= 1) {
        int v = (t >= o) ? p[t - o] : 0;
        __syncthreads();
        p[t] += v;
        __syncthreads();
    }
    int pre = bpre + ((t > 0) ? p[t - 1] : 0);
#pragma unroll
    for (int j = 0; j < SCAN_PER; j++) {
        int i = base + j;
        if (i < N_NODES) {
            int o = pre + loc[j];
            g_off[i] = o;
            g_cur[i] = o;
            g_dinv[i] = rsqrtf((float)(g_deg[i] + 1));  // +1 self loop
        }
    }
}

// counting-sort edges by dst into g_adj (re-decodes ei; norm precomputed)
__global__ void fill_kernel(const int* __restrict__ w) {
    int idx = blockIdx.x * 256 + threadIdx.x;
    int is64 = g_is64;
#pragma unroll
    for (int j = 0; j < 4; j++) {
        int e = idx + j * EDGE4_T;
        if (e < N_EDGES) {
            int s, d;
            if (is64) { s = w[2 * e]; d = w[2 * (N_EDGES + e)]; }
            else      { s = w[e];     d = w[N_EDGES + e]; }
            if ((unsigned)s >= N_NODES) s = 0;
            if ((unsigned)d >= N_NODES) d = 0;
            int pos = atomicAdd(&g_cur[d], 1);
            g_adj[pos] = make_int2(s, __float_as_int(g_dinv[s] * g_dinv[d]));
        }
    }
}

// ---------------- GEMM1: C[M,64] = A[M,128] * W[128,64] --------------------
// 128 rows/block, 256 threads, 4x8 micro-tile with packed fma.rn.f32x2.
__global__ void gemm1_kernel(const float* __restrict__ A,
                             const float* __restrict__ W,
                             float* __restrict__ C, int M) {
    constexpr int KDIM = IN_CH, NDIM = HIDDEN, ROWS = 128, NT = 256;
    constexpr int PITCH = KDIM + 4;
    extern __shared__ float smem[];
    float* sA = smem;                   // [128][132]
    float* sW = smem + ROWS * PITCH;    // [128][64]
    const int tid = threadIdx.x;
    const int rowbase = blockIdx.x * ROWS;

    for (int v = tid; v < KDIM * NDIM / 4; v += NT)
        ((float4*)sW)[v] = ((const float4*)W)[v];

    constexpr int KC4 = KDIM / 4;
    for (int v = tid; v < ROWS * KC4; v += NT) {
        int r  = v / KC4;
        int kc = (v - r * KC4) * 4;
        int row = rowbase + r;
        float4 a = make_float4(0.f, 0.f, 0.f, 0.f);
        if (row < M) a = *(const float4*)(A + (size_t)row * KDIM + kc);
        *(float4*)(sA + r * PITCH + kc) = a;
    }
    __syncthreads();

    const int ty = tid / 8, tx = tid & 7;   // 32 x 8
    unsigned long long acc[4][4];
#pragma unroll
    for (int i = 0; i < 4; i++)
#pragma unroll
        for (int j = 0; j < 4; j++) acc[i][j] = 0ull;

#pragma unroll 4
    for (int k = 0; k < KDIM; k++) {
        ulonglong2 b01 = *(const ulonglong2*)(sW + k * NDIM + 8 * tx);
        ulonglong2 b23 = *(const ulonglong2*)(sW + k * NDIM + 8 * tx + 4);
#pragma unroll
        for (int i = 0; i < 4; i++) {
            unsigned long long pa = pack2(sA[(4 * ty + i) * PITCH + k]);
            acc[i][0] = ffma2(pa, b01.x, acc[i][0]);
            acc[i][1] = ffma2(pa, b01.y, acc[i][1]);
            acc[i][2] = ffma2(pa, b23.x, acc[i][2]);
            acc[i][3] = ffma2(pa, b23.y, acc[i][3]);
        }
    }

#pragma unroll
    for (int i = 0; i < 4; i++) {
        int row = rowbase + 4 * ty + i;
        if (row < M) {
            ulonglong2* p = (ulonglong2*)(C + (size_t)row * NDIM + 8 * tx);
            p[0] = make_ulonglong2(acc[i][0], acc[i][1]);
            p[1] = make_ulonglong2(acc[i][2], acc[i][3]);
        }
    }
}

// ---------------- GEMM2: C[M,40] = relu(A[M,64]) * W[64,40] ----------------
__global__ void gemm2_kernel(const float* __restrict__ A,
                             const float* __restrict__ W,
                             float* __restrict__ C, int M) {
    constexpr int KDIM = HIDDEN, NDIM = NCLS, ROWS = 128;
    constexpr int TX = NDIM / 8, TY = ROWS / 4, NT = TX * TY;  // 5 x 32 = 160
    constexpr int PITCH = KDIM + 4;
    extern __shared__ float smem[];
    float* sA = smem;
    float* sW = smem + ROWS * PITCH;

    const int tid     = threadIdx.x;
    const int rowbase = blockIdx.x * ROWS;

    for (int v = tid; v < KDIM * NDIM / 4; v += NT)
        ((float4*)sW)[v] = ((const float4*)W)[v];

    constexpr int KC4 = KDIM / 4;
    for (int v = tid; v < ROWS * KC4; v += NT) {
        int r  = v / KC4;
        int kc = (v - r * KC4) * 4;
        int row = rowbase + r;
        float4 a = make_float4(0.f, 0.f, 0.f, 0.f);
        if (row < M) a = *(const float4*)(A + (size_t)row * KDIM + kc);
        a.x = fmaxf(a.x, 0.f); a.y = fmaxf(a.y, 0.f);
        a.z = fmaxf(a.z, 0.f); a.w = fmaxf(a.w, 0.f);
        *(float4*)(sA + r * PITCH + kc) = a;
    }
    __syncthreads();

    const int ty = tid / TX, tx = tid - (tid / TX) * TX;
    unsigned long long acc[4][4];
#pragma unroll
    for (int i = 0; i < 4; i++)
#pragma unroll
        for (int j = 0; j < 4; j++) acc[i][j] = 0ull;

#pragma unroll 4
    for (int k = 0; k < KDIM; k++) {
        ulonglong2 b01 = *(const ulonglong2*)(sW + k * NDIM + 8 * tx);
        ulonglong2 b23 = *(const ulonglong2*)(sW + k * NDIM + 8 * tx + 4);
#pragma unroll
        for (int i = 0; i < 4; i++) {
            unsigned long long pa = pack2(sA[(4 * ty + i) * PITCH + k]);
            acc[i][0] = ffma2(pa, b01.x, acc[i][0]);
            acc[i][1] = ffma2(pa, b01.y, acc[i][1]);
            acc[i][2] = ffma2(pa, b23.x, acc[i][2]);
            acc[i][3] = ffma2(pa, b23.y, acc[i][3]);
        }
    }

#pragma unroll
    for (int i = 0; i < 4; i++) {
        int row = rowbase + 4 * ty + i;
        if (row < M) {
            ulonglong2* p = (ulonglong2*)(C + (size_t)row * NDIM + 8 * tx);
            p[0] = make_ulonglong2(acc[i][0], acc[i][1]);
            p[1] = make_ulonglong2(acc[i][2], acc[i][3]);
        }
    }
}

// ---------------- CSR aggregation with adj prefetch -------------------------
// out[i] = bias + dinv_i^2*feat[i] + sum_j norm_ij*feat[src_j]
// one warp per node; lane groups of V4 lanes own float4 chunks; EP edges/iter.
template<int CH>
__global__ void aggregate_kernel(const float* __restrict__ feat,
                                 const float* __restrict__ bias,
                                 float* __restrict__ out) {
    constexpr int V4 = CH / 4;       // 16 (CH=64) or 10 (CH=40)
    constexpr int EP = 32 / V4;      // 2 or 3
    int node = (blockIdx.x * blockDim.x + threadIdx.x) >> 5;
    if (node >= N_NODES) return;
    int lane = threadIdx.x & 31;
    int eg = lane / V4;              // edge group
    int c  = lane - eg * V4;         // float4 index within row
    bool act = eg < EP;

    const int beg = g_off[node];
    const int end = g_off[node + 1];

    float4 acc = make_float4(0.f, 0.f, 0.f, 0.f);
    if (eg == 0) {                   // self-loop + bias in group 0 only
        float dv = g_dinv[node];
        float s  = dv * dv;
        float4 f  = ((const float4*)(feat + (size_t)node * CH))[c];
        float4 bb = ((const float4*)bias)[c];
        acc.x = fmaf(s, f.x, bb.x);
        acc.y = fmaf(s, f.y, bb.y);
        acc.z = fmaf(s, f.z, bb.z);
        acc.w = fmaf(s, f.w, bb.w);
    }

    // software-pipelined edge loop; dummy entries carry norm=0 (src=0 safe)
    int2 p = make_int2(0, 0);
    if (act && beg + eg < end) p = g_adj[beg + eg];
    for (int k = beg; k < end; k += EP) {
        int kn = k + EP;
        int2 pn = make_int2(0, 0);
        if (act && kn + eg < end) pn = g_adj[kn + eg];
        float nrm = __int_as_float(p.y);
        float4 v = ((const float4*)(feat + (size_t)p.x * CH))[c];
        acc.x = fmaf(nrm, v.x, acc.x);
        acc.y = fmaf(nrm, v.y, acc.y);
        acc.z = fmaf(nrm, v.z, acc.z);
        acc.w = fmaf(nrm, v.w, acc.w);
        p = pn;
    }

    // reduce groups 1..EP-1 into group 0 (shfls read pre-update values)
    const unsigned m = 0xffffffffu;
    float x1 = __shfl_down_sync(m, acc.x, V4);
    float y1 = __shfl_down_sync(m, acc.y, V4);
    float z1 = __shfl_down_sync(m, acc.z, V4);
    float w1 = __shfl_down_sync(m, acc.w, V4);
    if (EP > 2) {
        float x2 = __shfl_down_sync(m, acc.x, 2 * V4);
        float y2 = __shfl_down_sync(m, acc.y, 2 * V4);
        float z2 = __shfl_down_sync(m, acc.z, 2 * V4);
        float w2 = __shfl_down_sync(m, acc.w, 2 * V4);
        x1 += x2; y1 += y2; z1 += z2; w1 += w2;
    }
    acc.x += x1; acc.y += y1; acc.z += z1; acc.w += w1;

    if (eg == 0)
        ((float4*)(out + (size_t)node * CH))[c] = acc;
}

// ---------------- launch ----------------------------------------------------
extern "C" void kernel_launch(void* const* d_in, const int* in_sizes, int n_in,
                              void* d_out, int out_size) {
    const float* x  = (const float*)d_in[0];
    const int*   ei = (const int*)d_in[1];      // int32 words of edge_index (either dtype)
    const float* W1 = (const float*)d_in[2];
    const float* b1 = (const float*)d_in[3];
    const float* W2 = (const float*)d_in[4];
    const float* b2 = (const float*)d_in[5];
    float*       out = (float*)d_out;

    void *hw_p, *agg1_p, *h2w_p;
    cudaGetSymbolAddress(&hw_p,   g_hw);
    cudaGetSymbolAddress(&agg1_p, g_agg1);
    cudaGetSymbolAddress(&h2w_p,  g_h2w);

    constexpr int TPB = 256;
    const int nb_nodes = (N_NODES + TPB - 1) / TPB;

    // 1) zero degrees + detect dtype
    prep_kernel<<<nb_nodes, TPB>>>(ei);
    // 2) degree histogram
    deg_kernel<<<NB_EDGE4, 256>>>(ei);
    // 3-4) scan (B fused into C)
    scanA_kernel<<<SCAN_NB, SCAN_TPB>>>();
    scanC_kernel<<<SCAN_NB, SCAN_TPB>>>();
    // 5) counting sort into dst-grouped adjacency
    fill_kernel<<<NB_EDGE4, 256>>>(ei);

    // 6) gemm1: X @ W1
    constexpr int SMEM1 = (128 * (IN_CH + 4) + IN_CH * HIDDEN) * sizeof(float); // 100352
    cudaFuncSetAttribute(gemm1_kernel, cudaFuncAttributeMaxDynamicSharedMemorySize, SMEM1);
    gemm1_kernel<<<(N_NODES + 127) / 128, 256, SMEM1>>>(x, W1, (float*)hw_p, N_NODES);

    // 7) layer1 aggregation (+bias,+self)
    const int nb_warps = (N_NODES * 32 + TPB - 1) / TPB;  // 1 warp per node
    aggregate_kernel<HIDDEN><<<nb_warps, TPB>>>((const float*)hw_p, b1, (float*)agg1_p);

    // 8) gemm2 (relu fused into A-load)
    constexpr int SMEM2 = (128 * (HIDDEN + 4) + HIDDEN * NCLS) * sizeof(float); // 45056
    cudaFuncSetAttribute(gemm2_kernel, cudaFuncAttributeMaxDynamicSharedMemorySize, SMEM2);
    gemm2_kernel<<<(N_NODES + 127) / 128, 160, SMEM2>>>((const float*)agg1_p, W2,
                                                        (float*)h2w_p, N_NODES);

    // 9) layer2 aggregation -> output
    aggregate_kernel<NCLS><<<nb_warps, TPB>>>((const float*)h2w_p, b2, out);
}